// round 17
// baseline (speedup 1.0000x reference)
#include <cuda_runtime.h>

#define T_LEN   16777216
#define FULLMASK 0xffffffffu

#define BLOCKT   320                     // 10 warps
#define NT       2048                    // tiles = grid
#define NT_LOG2  11

// ---------------- halo path config ----------------
#define H_TILE   8192                    // output elems per tile (2048 quads)
#define H_HALOQ  256                     // halo quads (1024 elems)
#define H_SPANQ  (H_TILE / 4 + H_HALOQ)  // 2304 quads
#define H_NPH    8                       // 8 masked phases x 320 covers 2304
#define LASTQ    (T_LEN / 4 - 1)         // 4194303

// ---------------- fallback path config (works on tid < 256) ----------------
#define F_WORK   256
#define F_ITEMS  32
#define F_TILE   8192
#define F_NWARP  8
#define F_SMEM   ((F_TILE + F_TILE / 8) * 4)   // 36864 B padded buffer

__device__ unsigned g_ctr;
__device__ unsigned g_flag[NT];
__device__ float2   g_part[NT];
__device__ float2   g_incl[NT];

__device__ __forceinline__ unsigned ld_acquire(const unsigned* p) {
    unsigned v;
    asm volatile("ld.acquire.gpu.global.b32 %0, [%1];" : "=r"(v) : "l"(p) : "memory");
    return v;
}
__device__ __forceinline__ void st_release(unsigned* p, unsigned v) {
    asm volatile("st.release.gpu.global.b32 [%0], %1;" :: "l"(p), "r"(v) : "memory");
}
__device__ __forceinline__ float pow2k(float a, int k) {   // a^(2^k)
    #pragma unroll 1
    for (int i = 0; i < k; i++) a *= a;
    return a;
}
__device__ __forceinline__ float powi(float base, int e, int bits) {  // base^e
    float r = 1.f;
    #pragma unroll 1
    for (int k = 0; k < bits; k++) { if (e & 1) r *= base; base *= base; e >>= 1; }
    return r;
}
// Halo gate: a^1024 < 1e-4 (alpha > ~0.009). Norm-based truncation error:
// rel ~ sqrt(NT/(T*(1-a^2))) * a^H ~ 0.08 * 1e-4 = 8e-6 worst case — 100x
// under the 1e-3 threshold. For the observed alpha (~0.011), a^1024 ~ 1.2e-5.
__device__ __forceinline__ bool halo_active(float a) {
    return pow2k(a, 10) < 1e-4f;
}

__global__ __launch_bounds__(BLOCKT, 3) void ses_fused(
    const float* __restrict__ y, const float* __restrict__ alpha_p,
    float* __restrict__ out)
{
    extern __shared__ float sdyn[];            // fallback transpose buffer only
    __shared__ float sh_agg[80];               // region aggregates (halo path)
    __shared__ float sh_P[80];                 // region exclusive prefixes
    __shared__ float sh_wB[F_NWARP];           // fallback
    __shared__ float sh_carry;
    __shared__ unsigned sh_ticket;

    const int tid  = threadIdx.x;
    const int lane = tid & 31;
    const int wid  = tid >> 5;

    const float alpha = __ldg(alpha_p);
    const float a = 1.0f - alpha;
    const float a2 = a * a, a3 = a2 * a, a4 = a2 * a2;

    if (halo_active(a)) {
        // ====================================================================
        // HALO PATH — striped registers, no transpose, no inter-block deps.
        // Span = 2304 quads (256 halo + 2048 output) ending at tile end.
        // Region (j,w) = quads [320j+32w, +32) = 128 contiguous elems.
        // Region index r = 10j + wid; 72 active regions (Q < 2304).
        // ====================================================================
        const int tile  = blockIdx.x;
        const int baseQ = tile * (H_TILE / 4) - H_HALOQ;     // -256 at tile 0

        // ---- phase A: batch ALL striped loads (MLP=8, no shfl in between) ----
        float4 x[H_NPH];
        #pragma unroll
        for (int j = 0; j < H_NPH; j++) {
            const int Q  = j * BLOCKT + tid;
            const int gq = baseQ + Q;
            x[j] = (Q < H_SPANQ && gq >= 0)
                     ? reinterpret_cast<const float4*>(y)[gq]
                     : make_float4(0.f, 0.f, 0.f, 0.f);
        }

        // ---- phase B: in-quad serial scan + per-phase warp scan ----
        float exB[H_NPH];
        #pragma unroll
        for (int j = 0; j < H_NPH; j++) {
            float p0 = alpha * x[j].x;
            float p1 = fmaf(a, p0, alpha * x[j].y);
            float p2 = fmaf(a, p1, alpha * x[j].z);
            float p3 = fmaf(a, p2, alpha * x[j].w);
            x[j] = make_float4(p0, p1, p2, p3);          // local partials

            float B = p3;                                // quad aggregate
            float m = a4;
            #pragma unroll
            for (int d = 1; d < 32; d <<= 1) {
                float pB = __shfl_up_sync(FULLMASK, B, d);
                if (lane >= d) B = fmaf(m, pB, B);
                m = m * m;
            }
            float e = __shfl_up_sync(FULLMASK, B, 1);
            exB[j] = (lane == 0) ? 0.f : e;
            if (lane == 31) sh_agg[10 * j + wid] = B;    // region aggregate
        }
        __syncthreads();

        // ---- warp 0: exclusive prefix over 72 regions (ratio a^128) ----
        if (wid == 0) {
            const float a128  = pow2k(a4, 5);            // a^128
            const float a4096 = pow2k(a128, 5);          // group ratio
            const float Al = powi(a128, lane, 5);        // a^(128*lane)
            float carryB = 0.f;
            #pragma unroll
            for (int g = 0; g < 3; g++) {
                const int idx = 32 * g + lane;
                float Bv = (idx < 72) ? sh_agg[idx] : 0.f;
                float m = a128;
                #pragma unroll
                for (int d = 1; d < 32; d <<= 1) {
                    float pB = __shfl_up_sync(FULLMASK, Bv, d);
                    if (lane >= d) Bv = fmaf(m, pB, Bv);
                    m = m * m;
                }
                float ex = __shfl_up_sync(FULLMASK, Bv, 1);
                if (lane == 0) ex = 0.f;
                if (idx < 72) sh_P[idx] = fmaf(Al, carryB, ex);
                float tot = __shfl_sync(FULLMASK, Bv, 31);
                carryB = fmaf(a4096, carryB, tot);
            }
        }
        __syncthreads();

        // ---- apply carries + store striped directly from registers ----
        const float a4l = powi(a4, lane, 5);             // a^(4*lane)
        const float y0 = (tile == 0) ? __ldg(y) : 0.f;
        #pragma unroll
        for (int j = 0; j < H_NPH; j++) {
            const int Q = j * BLOCKT + tid;
            if (Q < H_HALOQ || Q >= H_SPANQ) continue;   // halo / masked tail
            const float cB = fmaf(a4l, sh_P[10 * j + wid], exB[j]);
            float e0 = fmaf(cB, a,  x[j].x);
            float e1 = fmaf(cB, a2, x[j].y);
            float e2 = fmaf(cB, a3, x[j].z);
            float e3 = fmaf(cB, a4, x[j].w);

            if (tile == 0) {                             // pin: s_t += a^(t+1)*y0
                float pw = a * powi(a4, Q - H_HALOQ, 11) * y0;
                e0 += pw; pw *= a;
                e1 += pw; pw *= a;
                e2 += pw; pw *= a;
                e3 += pw;
            }

            const long long gq = (long long)baseQ + Q;
            if (gq < (long long)LASTQ || tile != NT - 1) {
                __stcs(&reinterpret_cast<float4*>(out)[gq],
                       make_float4(e0, e1, e2, e3));
            } else {                                     // final quad: 3 elems
                float* op = out + 4 * gq;
                op[0] = e0; op[1] = e1; op[2] = e2;      // skip index T_LEN-1
            }
        }
        return;
    }

    // ========================================================================
    // FALLBACK PATH (tiny alpha): decoupled lookback, generation flags.
    // Work on tid < 256; warps 8-9 join barriers only. Buffer in dynamic SMEM.
    // ========================================================================
    float4* s4 = reinterpret_cast<float4*>(sdyn);        // padded: slot=Q+(Q>>3)

    if (tid == 0) sh_ticket = atomicAdd(&g_ctr, 1u);
    __syncthreads();
    const unsigned ticket = sh_ticket;
    const int tile = (int)(ticket & (NT - 1u));
    const unsigned fPart = 3u * (ticket >> NT_LOG2) + 1u;
    const unsigned fIncl = fPart + 1u;

    {
        const float4* yin = reinterpret_cast<const float4*>(y) + (size_t)tile * (F_TILE / 4);
        #pragma unroll
        for (int j = 0; j < 7; j++) {
            const int Q = j * BLOCKT + tid;
            if (Q < F_TILE / 4) s4[Q + (Q >> 3)] = yin[Q];
        }
    }
    __syncthreads();

    const float a8 = a4 * a4, a16 = a8 * a8;
    const float a32 = a16 * a16;

    float v[F_ITEMS];
    float B = 0.f, TexA = 1.f, TexB = 0.f, A1024 = 0.f;
    if (tid < F_WORK) {
        #pragma unroll
        for (int i = 0; i < 8; i++) {
            const int Q = 8 * tid + i;
            float4 q = s4[Q + (Q >> 3)];
            v[4*i+0] = q.x; v[4*i+1] = q.y; v[4*i+2] = q.z; v[4*i+3] = q.w;
        }
        {
            float p = 0.f;
            const bool first = (tile == 0 && tid == 0);
            #pragma unroll
            for (int i = 0; i < F_ITEMS; i++) {
                float aa = a, bb = alpha * v[i];
                if (first && i == 0) { aa = 0.f; bb = v[0]; }
                p = fmaf(aa, p, bb);
                v[i] = p;
            }
            B = p;
        }
        float m = a32;
        #pragma unroll
        for (int d = 1; d < 32; d <<= 1) {
            float pB = __shfl_up_sync(FULLMASK, B, d);
            if (lane >= d) B = fmaf(m, pB, B);
            m = m * m;
        }
        A1024 = m;
        if (lane == 31) sh_wB[wid] = B;
    }
    __syncthreads();

    if (tid < F_WORK) {
        float WB = 0.f;
        #pragma unroll
        for (int w = 0; w < F_NWARP; w++) if (w < wid) WB = fmaf(A1024, WB, sh_wB[w]);
        const float exA = powi(a32, lane, 5);
        float exB2 = __shfl_up_sync(FULLMASK, B, 1);
        if (lane == 0) exB2 = 0.f;
        TexB = fmaf(exA, WB, exB2);
        TexA = exA * powi(A1024, wid, 3);
    }

    float aggA = 0.f, aggB = 0.f;
    if (tid == 0) {
        float gB = 0.f;
        #pragma unroll
        for (int w = 0; w < F_NWARP; w++) gB = fmaf(A1024, gB, sh_wB[w]);
        float A8192 = A1024 * A1024; A8192 *= A8192; A8192 *= A8192;
        aggA = (tile == 0) ? 0.f : A8192;
        aggB = gB;
        if (tile == 0) {
            __stcg(&g_incl[0], make_float2(0.f, gB));
            st_release(&g_flag[0], fIncl);
            sh_carry = 0.f;
        } else {
            __stcg(&g_part[tile], make_float2(A8192, gB));
            st_release(&g_flag[tile], fPart);
        }
    }

    if (wid == 0 && tile > 0) {
        __syncwarp();
        float accA, accB;
        bool done;
        int pred = tile - 1;
        {   // fast path: wait only on the IMMEDIATE predecessor
            unsigned f = ld_acquire(&g_flag[pred]);
            while (f < fPart) { __nanosleep(32); f = ld_acquire(&g_flag[pred]); }
            float2 d2 = (f >= fIncl) ? __ldcg(&g_incl[pred]) : __ldcg(&g_part[pred]);
            accA = d2.x; accB = d2.y;
            done = (f >= fIncl) || (accA == 0.0f);
            pred--;
        }
        while (!done) {
            const int idx = pred - lane;
            unsigned st = 2u;
            if (idx >= 0) {
                unsigned f = ld_acquire(&g_flag[idx]);
                while (f < fPart) { __nanosleep(32); f = ld_acquire(&g_flag[idx]); }
                st = f - fPart + 1u;
            }
            float mA, mB;
            if (idx < 0) { mA = 1.f; mB = 0.f; }
            else {
                float2 d2 = (st == 2u) ? __ldcg(&g_incl[idx]) : __ldcg(&g_part[idx]);
                mA = d2.x; mB = d2.y;
            }
            const unsigned bal = __ballot_sync(FULLMASK, st == 2u);
            const int mm = bal ? (__ffs(bal) - 1) : 32;
            const int start = (mm < 32) ? mm : 31;

            float cA = 1.f, cB = 0.f;                // window earliest->latest
            for (int L = start; L >= 0; --L) {
                float sA = __shfl_sync(FULLMASK, mA, L);
                float sB = __shfl_sync(FULLMASK, mB, L);
                cB = fmaf(sA, cB, sB);
                cA = cA * sA;
            }
            float nB = fmaf(accA, cB, accB);         // acc = combine(window, acc)
            accA = cA * accA;
            accB = nB;
            done = (mm < 32) || (accA == 0.0f);
            pred -= 32;
        }
        if (lane == 0) {
            __stcg(&g_incl[tile], make_float2(accA * aggA, fmaf(aggA, accB, aggB)));
            st_release(&g_flag[tile], fIncl);
            sh_carry = accB;
        }
    }
    __syncthreads();

    if (tid < F_WORK) {
        const float c = fmaf(TexA, sh_carry, TexB);
        float cp = c * a;
        #pragma unroll
        for (int i = 0; i < F_ITEMS; i++) { v[i] += cp; cp *= a; }
        #pragma unroll
        for (int i = 0; i < 8; i++) {
            const int Q = 8 * tid + i;
            s4[Q + (Q >> 3)] = make_float4(v[4*i+0], v[4*i+1], v[4*i+2], v[4*i+3]);
        }
    }
    __syncthreads();

    {
        float4* o4 = reinterpret_cast<float4*>(out) + (size_t)tile * (F_TILE / 4);
        if (tile != NT - 1) {
            #pragma unroll
            for (int j = 0; j < 7; j++) {
                const int Q = j * BLOCKT + tid;
                if (Q < F_TILE / 4) __stcs(&o4[Q], s4[Q + (Q >> 3)]);
            }
        } else {
            const long long tbase = (long long)tile * F_TILE;
            #pragma unroll
            for (int j = 0; j < 7; j++) {
                const int Q = j * BLOCKT + tid;
                if (Q >= F_TILE / 4) continue;
                float4 q = s4[Q + (Q >> 3)];
                const long long g = tbase + 4LL * Q;
                if (g + 4 <= (long long)(T_LEN - 1)) {
                    __stcs(&o4[Q], q);
                } else {
                    float* op = out + g;
                    if (g + 0 < (long long)(T_LEN - 1)) op[0] = q.x;
                    if (g + 1 < (long long)(T_LEN - 1)) op[1] = q.y;
                    if (g + 2 < (long long)(T_LEN - 1)) op[2] = q.z;
                    if (g + 3 < (long long)(T_LEN - 1)) op[3] = q.w;
                }
            }
        }
    }
}

extern "C" void kernel_launch(void* const* d_in, const int* in_sizes, int n_in,
                              void* d_out, int out_size) {
    const float* y     = (const float*)d_in[0];   // timeseries, T_LEN fp32
    const float* alpha = (const float*)d_in[1];   // 1 fp32
    float* out = (float*)d_out;                   // T_LEN-1 fp32
    (void)in_sizes; (void)n_in; (void)out_size;

    ses_fused<<<NT, BLOCKT, F_SMEM>>>(y, alpha, out);
}